// round 13
// baseline (speedup 1.0000x reference)
#include <cuda_runtime.h>
#include <cuda_fp16.h>
#include <cstdint>

// Problem dims (fixed)
#define BDIM 256
#define TDIM 500
#define IDIM 1024
#define ODIM 2048
#define M_GEMM (BDIM * TDIM)   // 128000
#define N_GEMM ODIM            // 2048
#define K_GEMM IDIM            // 1024

// GEMM tiling: 128x128 CTA tile, 128 threads, 4 warps 2(m) x 2(n), 64x64/warp
#define BM 128
#define BN 128
#define BK 64
#define STAGES 3
#define NCHUNK (K_GEMM / BK)   // 16
#define MTILES 4               // 4 x 128 T-rows per CTA (500 clamped to 512)
#define NTHREADS 128

// Padded smem strides (bytes): 16B-chunk counts == 1 mod 8 -> conflict-free ldmatrix
#define A_STRIDE 144           // 64 halves (128B) + 16B pad  (9 chunks)
#define B_STRIDE 272           // 128 halves (256B) + 16B pad (17 chunks)
#define A_STAGE_BYTES (128 * A_STRIDE)   // 18432
#define B_STAGE_BYTES (64 * B_STRIDE)    // 17408
#define STAGE_BYTES (A_STAGE_BYTES + B_STAGE_BYTES)  // 35840
#define SMEM_TOTAL (STAGES * STAGE_BYTES)            // 107520 (2 CTA/SM)

// Scan buffer: fp32 h-tile 128x128, pitch 132 floats (67584 B) in stages 1..2.
#define BUF_OFF  STAGE_BYTES
#define BUF_PITCH 132

// Device scratch (no runtime allocation allowed)
__device__ __align__(1024) __half g_xh[(size_t)M_GEMM * K_GEMM];  // 256 MB
__device__ __align__(1024) __half g_wh[(size_t)K_GEMM * N_GEMM];  // 4 MB

// ---------------------------------------------------------------------------
__device__ __forceinline__ uint32_t smem_u32(const void* p) {
    uint32_t a;
    asm("{ .reg .u64 t; cvta.to.shared.u64 t, %1; cvt.u32.u64 %0, t; }" : "=r"(a) : "l"(p));
    return a;
}
__device__ __forceinline__ void cp16(uint32_t dst, const void* src) {
    asm volatile("cp.async.cg.shared.global [%0], [%1], 16;" :: "r"(dst), "l"(src));
}
#define CP_COMMIT() asm volatile("cp.async.commit_group;" ::: "memory")

__device__ __forceinline__ void ldsm_x4(uint32_t* r, uint32_t addr) {
    asm volatile("ldmatrix.sync.aligned.m8n8.x4.shared.b16 {%0,%1,%2,%3}, [%4];"
                 : "=r"(r[0]), "=r"(r[1]), "=r"(r[2]), "=r"(r[3]) : "r"(addr));
}
__device__ __forceinline__ void ldsm_x4_t(uint32_t* r, uint32_t addr) {
    asm volatile("ldmatrix.sync.aligned.m8n8.x4.trans.shared.b16 {%0,%1,%2,%3}, [%4];"
                 : "=r"(r[0]), "=r"(r[1]), "=r"(r[2]), "=r"(r[3]) : "r"(addr));
}
__device__ __forceinline__ void mma16816(float* c, const uint32_t* a, uint32_t b0, uint32_t b1) {
    asm volatile(
        "mma.sync.aligned.m16n8k16.row.col.f32.f16.f16.f32 "
        "{%0,%1,%2,%3}, {%4,%5,%6,%7}, {%8,%9}, {%0,%1,%2,%3};"
        : "+f"(c[0]), "+f"(c[1]), "+f"(c[2]), "+f"(c[3])
        : "r"(a[0]), "r"(a[1]), "r"(a[2]), "r"(a[3]), "r"(b0), "r"(b1));
}

// ---------------------------------------------------------------------------
// Pre-pass: fp32 -> fp16 conversions
// ---------------------------------------------------------------------------
__global__ void cvt_x_kernel(const float* __restrict__ x) {
    const size_t total4 = (size_t)M_GEMM * K_GEMM / 4;
    size_t stride = (size_t)gridDim.x * blockDim.x;
    for (size_t i = (size_t)blockIdx.x * blockDim.x + threadIdx.x; i < total4; i += stride) {
        float4 v = __ldg((const float4*)x + i);
        __half2* dst = (__half2*)(g_xh + i * 4);
        dst[0] = __floats2half2_rn(v.x, v.y);
        dst[1] = __floats2half2_rn(v.z, v.w);
    }
}
__global__ void cvt_w_kernel(const float* __restrict__ w) {
    const size_t total4 = (size_t)K_GEMM * N_GEMM / 4;
    size_t stride = (size_t)gridDim.x * blockDim.x;
    for (size_t i = (size_t)blockIdx.x * blockDim.x + threadIdx.x; i < total4; i += stride) {
        float4 v = __ldg((const float4*)w + i);
        __half2* dst = (__half2*)(g_wh + i * 4);
        dst[0] = __floats2half2_rn(v.x, v.y);
        dst[1] = __floats2half2_rn(v.z, v.w);
    }
}

// ---------------------------------------------------------------------------
// Fused GEMM + scan. CTA = (batch b, 128-col N-block). 4 M-tiles of 128 T-rows.
// ---------------------------------------------------------------------------
__device__ __forceinline__ void issue_loads(int tid, int t0, int chunk,
                                            const __half* aSrc, int block_n,
                                            uint32_t smem_base) {
    const int k0 = chunk * BK;
    const uint32_t sb = smem_base + (chunk % STAGES) * STAGE_BYTES;
#pragma unroll
    for (int i = 0; i < 8; i++) {   // A: 128 rows x 128B = 1024 x 16B (8/thread)
        int idx = tid + i * NTHREADS;
        int r = idx >> 3, q = idx & 7;
        int t = t0 + r; if (t > TDIM - 1) t = TDIM - 1;
        cp16(sb + r * A_STRIDE + q * 16,
             aSrc + (size_t)t * K_GEMM + k0 + q * 8);
    }
#pragma unroll
    for (int i = 0; i < 8; i++) {   // B: 64 rows x 256B = 1024 x 16B (8/thread)
        int idx = tid + i * NTHREADS;
        int r = idx >> 4, q = idx & 15;
        cp16(sb + A_STAGE_BYTES + r * B_STRIDE + q * 16,
             g_wh + (size_t)(k0 + r) * N_GEMM + block_n + q * 8);
    }
    CP_COMMIT();
}

__global__ void __launch_bounds__(128, 2)
fused_gemm_scan_kernel(const float* __restrict__ alpha,
                       const float* __restrict__ beta,
                       float* __restrict__ out) {
    extern __shared__ char smem[];
    const uint32_t sbase = smem_u32(smem);
    float* buf = (float*)(smem + BUF_OFF);

    const int tid  = threadIdx.x;
    const int wid  = tid >> 5;        // 0..3
    const int lane = tid & 31;
    const int wm = wid >> 1;          // 0..1  (64-row slab)
    const int wn = wid & 1;           // 0..1  (64-col slab)
    const int b       = blockIdx.y;
    const int block_n = blockIdx.x * BN;
    const __half* aSrc = g_xh + (size_t)b * TDIM * K_GEMM;
    float* outB = out + (size_t)b * TDIM * ODIM + block_n;

    // scan state: each of the 128 threads owns one output column
    float syn = 0.0f;
    const float decay = alpha[block_n + tid] * (1.0f - beta[block_n + tid]);

    const int a_row  = wm * 64 + (lane & 15);               // + mf*16
    const int a_colb = ((lane >> 4) & 1) * 16;              // bytes; + ks*32
    const int b_krow = (lane & 7) + ((lane >> 3) & 1) * 8;  // + ks*16
    const int b_ncol = wn * 64 + ((lane >> 4) & 1) * 8;     // + p*16
    const int m0l = wm * 64 + (lane >> 2);
    const int n0l = wn * 64 + (lane & 3) * 2;

    // Pre-issue tile 0 chunk 0 (stage 0)
    issue_loads(tid, 0, 0, aSrc, block_n, sbase);

#pragma unroll 1
    for (int tile = 0; tile < MTILES; tile++) {
        const int t0 = tile * BM;
        float c[4][8][4] = {};        // 128 accumulators (64x64 warp tile)

        // chunk 1 prologue (chunk 0 prefetched before the previous scan)
        issue_loads(tid, t0, 1, aSrc, block_n, sbase);

#pragma unroll 1
        for (int ch = 0; ch < NCHUNK; ch++) {
            asm volatile("cp.async.wait_group 1;" ::: "memory");
            __syncthreads();

            if (ch + STAGES - 1 < NCHUNK)
                issue_loads(tid, t0, ch + STAGES - 1, aSrc, block_n, sbase);
            else
                CP_COMMIT();   // keep group-count invariant

            const uint32_t aB = sbase + (ch % STAGES) * STAGE_BYTES;
            const uint32_t bB = aB + A_STAGE_BYTES;

#pragma unroll
            for (int ks = 0; ks < 4; ks++) {
                uint32_t a[4][4], bb[4][4];
#pragma unroll
                for (int mf = 0; mf < 4; mf++)
                    ldsm_x4(a[mf], aB + (a_row + mf * 16) * A_STRIDE + ks * 32 + a_colb);
#pragma unroll
                for (int p = 0; p < 4; p++)
                    ldsm_x4_t(bb[p], bB + (b_krow + ks * 16) * B_STRIDE
                                       + (b_ncol + p * 16) * 2);
#pragma unroll
                for (int mf = 0; mf < 4; mf++)
#pragma unroll
                    for (int nf = 0; nf < 8; nf++)
                        mma16816(c[mf][nf], a[mf],
                                 bb[nf >> 1][(nf & 1) * 2], bb[nf >> 1][(nf & 1) * 2 + 1]);
            }
        }

        // Barrier BEFORE any stage overwrite (stage-0 WAR fix from R11)
        __syncthreads();

        // Prefetch next tile's chunk 0 into stage 0 (disjoint from scan buffer)
        if (tile + 1 < MTILES)
            issue_loads(tid, t0 + BM, 0, aSrc, block_n, sbase);
        else
            CP_COMMIT();

        // Accumulators -> fp32 smem buffer (pitch 132 floats)
#pragma unroll
        for (int mf = 0; mf < 4; mf++) {
#pragma unroll
            for (int nf = 0; nf < 8; nf++) {
                int r0 = m0l + mf * 16;
                int cc = n0l + nf * 8;
                *(float2*)(buf + r0 * BUF_PITCH + cc) =
                    make_float2(c[mf][nf][0], c[mf][nf][1]);
                *(float2*)(buf + (r0 + 8) * BUF_PITCH + cc) =
                    make_float2(c[mf][nf][2], c[mf][nf][3]);
            }
        }
        __syncthreads();

        // Sequential scan over this tile's 128 T-steps (all 128 threads)
        {
            if (tile == 0) outB[tid] = 0.0f;   // out[b, 0, :] = 0
#pragma unroll 4
            for (int i = 0; i < BM; i++) {
                int t_out = t0 + i + 1;
                if (t_out < TDIM) {
                    syn = fmaf(decay, syn, buf[i * BUF_PITCH + tid]);
                    outB[(size_t)t_out * ODIM + tid] = syn;
                }
            }
        }
        __syncthreads();   // scan done -> next tile may overwrite buf stages
    }
}

// ---------------------------------------------------------------------------
extern "C" void kernel_launch(void* const* d_in, const int* in_sizes, int n_in,
                              void* d_out, int out_size)
{
    const float* x     = (const float*)d_in[0];
    const float* w     = (const float*)d_in[1];
    const float* alpha = (const float*)d_in[2];
    const float* beta  = (const float*)d_in[3];
    float* out         = (float*)d_out;

    cudaFuncSetAttribute(fused_gemm_scan_kernel,
                         cudaFuncAttributeMaxDynamicSharedMemorySize, SMEM_TOTAL);

    cvt_x_kernel<<<4096, 256>>>(x);
    cvt_w_kernel<<<512, 256>>>(w);

    dim3 grid(N_GEMM / BN, BDIM);   // (16, 256); x-fast => A-panel L2 reuse
    fused_gemm_scan_kernel<<<grid, NTHREADS, SMEM_TOTAL>>>(alpha, beta, out);
}

// round 16
// speedup vs baseline: 1.0914x; 1.0914x over previous
#include <cuda_runtime.h>
#include <cuda_fp16.h>
#include <cstdint>

// Problem dims (fixed)
#define BDIM 256
#define TDIM 500
#define IDIM 1024
#define ODIM 2048
#define M_GEMM (BDIM * TDIM)   // 128000
#define N_GEMM ODIM            // 2048
#define K_GEMM IDIM            // 1024

// GEMM tiling: 128x128 CTA tile, 128 threads, 4 warps 2(m) x 2(n), 64x64/warp
// 2 pipeline stages, 3 CTAs/SM (71.7KB smem, <=170 regs)
#define BM 128
#define BN 128
#define BK 64
#define STAGES 2
#define NCHUNK (K_GEMM / BK)   // 16
#define MTILES 4               // 4 x 128 T-rows per CTA (500 clamped to 512)
#define NTHREADS 128

// Padded smem strides (bytes): 16B-chunk counts == 1 mod 8 -> conflict-free ldmatrix
#define A_STRIDE 144           // 64 halves (128B) + 16B pad  (9 chunks)
#define B_STRIDE 272           // 128 halves (256B) + 16B pad (17 chunks)
#define A_STAGE_BYTES (128 * A_STRIDE)   // 18432
#define B_STAGE_BYTES (64 * B_STRIDE)    // 17408
#define STAGE_BYTES (A_STAGE_BYTES + B_STAGE_BYTES)  // 35840
#define SMEM_TOTAL (STAGES * STAGE_BYTES)            // 71680 (3 CTA/SM: 215KB)

// Scan buffer: fp16 h-tile 128x128, pitch 136 halves (34816 B) -> fits stage 1.
// Stage 0 stays free for the cross-tile chunk-0 prefetch.
#define BUF_OFF  STAGE_BYTES
#define BUF_PITCH 136          // halves

// Device scratch (no runtime allocation allowed)
__device__ __align__(1024) __half g_xh[(size_t)M_GEMM * K_GEMM];  // 256 MB
__device__ __align__(1024) __half g_wh[(size_t)K_GEMM * N_GEMM];  // 4 MB

// ---------------------------------------------------------------------------
__device__ __forceinline__ uint32_t smem_u32(const void* p) {
    uint32_t a;
    asm("{ .reg .u64 t; cvta.to.shared.u64 t, %1; cvt.u32.u64 %0, t; }" : "=r"(a) : "l"(p));
    return a;
}
__device__ __forceinline__ void cp16(uint32_t dst, const void* src) {
    asm volatile("cp.async.cg.shared.global [%0], [%1], 16;" :: "r"(dst), "l"(src));
}
#define CP_COMMIT() asm volatile("cp.async.commit_group;" ::: "memory")

__device__ __forceinline__ void ldsm_x4(uint32_t* r, uint32_t addr) {
    asm volatile("ldmatrix.sync.aligned.m8n8.x4.shared.b16 {%0,%1,%2,%3}, [%4];"
                 : "=r"(r[0]), "=r"(r[1]), "=r"(r[2]), "=r"(r[3]) : "r"(addr));
}
__device__ __forceinline__ void ldsm_x4_t(uint32_t* r, uint32_t addr) {
    asm volatile("ldmatrix.sync.aligned.m8n8.x4.trans.shared.b16 {%0,%1,%2,%3}, [%4];"
                 : "=r"(r[0]), "=r"(r[1]), "=r"(r[2]), "=r"(r[3]) : "r"(addr));
}
__device__ __forceinline__ void mma16816(float* c, const uint32_t* a, uint32_t b0, uint32_t b1) {
    asm volatile(
        "mma.sync.aligned.m16n8k16.row.col.f32.f16.f16.f32 "
        "{%0,%1,%2,%3}, {%4,%5,%6,%7}, {%8,%9}, {%0,%1,%2,%3};"
        : "+f"(c[0]), "+f"(c[1]), "+f"(c[2]), "+f"(c[3])
        : "r"(a[0]), "r"(a[1]), "r"(a[2]), "r"(a[3]), "r"(b0), "r"(b1));
}

// ---------------------------------------------------------------------------
// Pre-pass: fp32 -> fp16 conversions
// ---------------------------------------------------------------------------
__global__ void cvt_x_kernel(const float* __restrict__ x) {
    const size_t total4 = (size_t)M_GEMM * K_GEMM / 4;
    size_t stride = (size_t)gridDim.x * blockDim.x;
    for (size_t i = (size_t)blockIdx.x * blockDim.x + threadIdx.x; i < total4; i += stride) {
        float4 v = __ldg((const float4*)x + i);
        __half2* dst = (__half2*)(g_xh + i * 4);
        dst[0] = __floats2half2_rn(v.x, v.y);
        dst[1] = __floats2half2_rn(v.z, v.w);
    }
}
__global__ void cvt_w_kernel(const float* __restrict__ w) {
    const size_t total4 = (size_t)K_GEMM * N_GEMM / 4;
    size_t stride = (size_t)gridDim.x * blockDim.x;
    for (size_t i = (size_t)blockIdx.x * blockDim.x + threadIdx.x; i < total4; i += stride) {
        float4 v = __ldg((const float4*)w + i);
        __half2* dst = (__half2*)(g_wh + i * 4);
        dst[0] = __floats2half2_rn(v.x, v.y);
        dst[1] = __floats2half2_rn(v.z, v.w);
    }
}

// ---------------------------------------------------------------------------
// Fused GEMM + scan. CTA = (batch b, 128-col N-block). 4 M-tiles of 128 T-rows.
// ---------------------------------------------------------------------------
__device__ __forceinline__ void issue_loads(int tid, int t0, int chunk,
                                            const __half* aSrc, int block_n,
                                            uint32_t smem_base) {
    const int k0 = chunk * BK;
    const uint32_t sb = smem_base + (chunk & 1) * STAGE_BYTES;
#pragma unroll
    for (int i = 0; i < 8; i++) {   // A: 128 rows x 128B = 1024 x 16B (8/thread)
        int idx = tid + i * NTHREADS;
        int r = idx >> 3, q = idx & 7;
        int t = t0 + r; if (t > TDIM - 1) t = TDIM - 1;
        cp16(sb + r * A_STRIDE + q * 16,
             aSrc + (size_t)t * K_GEMM + k0 + q * 8);
    }
#pragma unroll
    for (int i = 0; i < 8; i++) {   // B: 64 rows x 256B = 1024 x 16B (8/thread)
        int idx = tid + i * NTHREADS;
        int r = idx >> 4, q = idx & 15;
        cp16(sb + A_STAGE_BYTES + r * B_STRIDE + q * 16,
             g_wh + (size_t)(k0 + r) * N_GEMM + block_n + q * 8);
    }
    CP_COMMIT();
}

__global__ void __launch_bounds__(128, 3)
fused_gemm_scan_kernel(const float* __restrict__ alpha,
                       const float* __restrict__ beta,
                       float* __restrict__ out) {
    extern __shared__ char smem[];
    const uint32_t sbase = smem_u32(smem);
    __half* buf = (__half*)(smem + BUF_OFF);   // stage 1 (chunk-15 data, recycled)

    const int tid  = threadIdx.x;
    const int wid  = tid >> 5;        // 0..3
    const int lane = tid & 31;
    const int wm = wid >> 1;          // 0..1  (64-row slab)
    const int wn = wid & 1;           // 0..1  (64-col slab)
    const int b       = blockIdx.y;
    const int block_n = blockIdx.x * BN;
    const __half* aSrc = g_xh + (size_t)b * TDIM * K_GEMM;
    float* outB = out + (size_t)b * TDIM * ODIM + block_n;

    // scan state: each of the 128 threads owns one output column
    float syn = 0.0f;
    const float decay = alpha[block_n + tid] * (1.0f - beta[block_n + tid]);

    const int a_row  = wm * 64 + (lane & 15);               // + mf*16
    const int a_colb = ((lane >> 4) & 1) * 16;              // bytes; + ks*32
    const int b_krow = (lane & 7) + ((lane >> 3) & 1) * 8;  // + ks*16
    const int b_ncol = wn * 64 + ((lane >> 4) & 1) * 8;     // + p*16
    const int m0l = wm * 64 + (lane >> 2);
    const int n0l = wn * 64 + (lane & 3) * 2;

    // Pre-issue tile 0 chunk 0 (stage 0)
    issue_loads(tid, 0, 0, aSrc, block_n, sbase);

#pragma unroll 1
    for (int tile = 0; tile < MTILES; tile++) {
        const int t0 = tile * BM;
        float c[4][8][4] = {};        // 128 accumulators (64x64 warp tile)

#pragma unroll 1
        for (int ch = 0; ch < NCHUNK; ch++) {
            // Barrier: previous users of stage (ch+1)&1 are done
            // (iter 0: also orders prior scan reads before ch1 overwrites buf/stage1)
            __syncthreads();

            if (ch + 1 < NCHUNK)
                issue_loads(tid, t0, ch + 1, aSrc, block_n, sbase);
            else
                CP_COMMIT();   // dummy: keeps wait_group 1 => chunk ch landed

            // wait all but newest group => chunk ch's data is in smem
            asm volatile("cp.async.wait_group 1;" ::: "memory");

            const uint32_t aB = sbase + (ch & 1) * STAGE_BYTES;
            const uint32_t bB = aB + A_STAGE_BYTES;

#pragma unroll
            for (int ks = 0; ks < 4; ks++) {
                uint32_t a[4][4], bb[4][4];
#pragma unroll
                for (int mf = 0; mf < 4; mf++)
                    ldsm_x4(a[mf], aB + (a_row + mf * 16) * A_STRIDE + ks * 32 + a_colb);
#pragma unroll
                for (int p = 0; p < 4; p++)
                    ldsm_x4_t(bb[p], bB + (b_krow + ks * 16) * B_STRIDE
                                       + (b_ncol + p * 16) * 2);
#pragma unroll
                for (int mf = 0; mf < 4; mf++)
#pragma unroll
                    for (int nf = 0; nf < 8; nf++)
                        mma16816(c[mf][nf], a[mf],
                                 bb[nf >> 1][(nf & 1) * 2], bb[nf >> 1][(nf & 1) * 2 + 1]);
            }
        }

        // All warps done reading both stages before any overwrite
        __syncthreads();

        // Prefetch next tile's chunk 0 into stage 0 (buf lives in stage 1)
        if (tile + 1 < MTILES)
            issue_loads(tid, t0 + BM, 0, aSrc, block_n, sbase);
        else
            CP_COMMIT();

        // Accumulators -> fp16 smem buffer (pitch 136 halves)
#pragma unroll
        for (int mf = 0; mf < 4; mf++) {
#pragma unroll
            for (int nf = 0; nf < 8; nf++) {
                int r0 = m0l + mf * 16;
                int cc = n0l + nf * 8;
                *(__half2*)(buf + r0 * BUF_PITCH + cc) =
                    __floats2half2_rn(c[mf][nf][0], c[mf][nf][1]);
                *(__half2*)(buf + (r0 + 8) * BUF_PITCH + cc) =
                    __floats2half2_rn(c[mf][nf][2], c[mf][nf][3]);
            }
        }
        __syncthreads();

        // Sequential scan over this tile's 128 T-steps (all 128 threads)
        {
            if (tile == 0) outB[tid] = 0.0f;   // out[b, 0, :] = 0
#pragma unroll 4
            for (int i = 0; i < BM; i++) {
                int t_out = t0 + i + 1;
                if (t_out < TDIM) {
                    syn = fmaf(decay, syn, __half2float(buf[i * BUF_PITCH + tid]));
                    outB[(size_t)t_out * ODIM + tid] = syn;
                }
            }
        }
        // NOTE: no barrier here; the sync at iter 0 of the next tile's chunk
        // loop orders these buf reads before chunk 1 overwrites stage 1.
    }
}

// ---------------------------------------------------------------------------
extern "C" void kernel_launch(void* const* d_in, const int* in_sizes, int n_in,
                              void* d_out, int out_size)
{
    const float* x     = (const float*)d_in[0];
    const float* w     = (const float*)d_in[1];
    const float* alpha = (const float*)d_in[2];
    const float* beta  = (const float*)d_in[3];
    float* out         = (float*)d_out;

    cudaFuncSetAttribute(fused_gemm_scan_kernel,
                         cudaFuncAttributeMaxDynamicSharedMemorySize, SMEM_TOTAL);

    cvt_x_kernel<<<4096, 256>>>(x);
    cvt_w_kernel<<<512, 256>>>(w);

    dim3 grid(N_GEMM / BN, BDIM);   // (16, 256); x-fast => A-panel L2 reuse
    fused_gemm_scan_kernel<<<grid, NTHREADS, SMEM_TOTAL>>>(alpha, beta, out);
}